// round 3
// baseline (speedup 1.0000x reference)
#include <cuda_runtime.h>
#include <math.h>

// Problem constants
constexpr int B_  = 4;
constexpr int S_  = 2048;
constexpr int D_  = 1024;
constexpr int H_  = 16;
constexpr int DK_ = 64;

// Scratch (device globals: allocation-free rule)
__device__ float g_Q[(size_t)B_ * H_ * S_ * DK_];    // [B,H,S,64]
__device__ float g_K[(size_t)B_ * H_ * S_ * DK_];
__device__ float g_V[(size_t)B_ * H_ * S_ * DK_];
__device__ float g_cat[(size_t)B_ * S_ * D_];        // attention out, concat layout [B,S,D]

// ---------------------------------------------------------------------------
// Tiled fp32 GEMM: C[M=8192, N=1024] = A[8192,1024] @ W + bias
// PERHEAD=1: W is [H][1024][64] (per-head stacked), C written as [B,H,S,64]
// PERHEAD=0: W is [1024][1024] row-major, C written as [8192,1024]
// Block tile 64x64, K-chunk 16, 256 threads, 4x4 per-thread micro-tile.
// ---------------------------------------------------------------------------
template <int PERHEAD>
__global__ __launch_bounds__(256) void proj_gemm(const float* __restrict__ A,
                                                 const float* __restrict__ W,
                                                 const float* __restrict__ bias,
                                                 float* __restrict__ C) {
    __shared__ float As[16][65];  // A tile transposed: As[kk][m], pad to reduce store conflicts
    __shared__ float Ws[16][64];  // W tile: Ws[kk][n]

    const int tid = threadIdx.x;
    const int tx = tid & 15;
    const int ty = tid >> 4;
    const int m0 = blockIdx.y << 6;
    const int n0 = blockIdx.x << 6;

    const float* Wb;
    int wstride;
    if (PERHEAD) { Wb = W + (size_t)(n0 >> 6) * (D_ * DK_); wstride = DK_; }
    else         { Wb = W + n0;                              wstride = D_;  }

    float acc[4][4] = {};

    const int ar  = tid >> 2;          // 0..63 row within A tile
    const int ac4 = (tid & 3) << 2;    // k offset 0,4,8,12
    const int wk  = tid >> 4;          // 0..15 k row within W tile
    const int wc4 = (tid & 15) << 2;   // n offset 0..60

    for (int k0 = 0; k0 < D_; k0 += 16) {
        float4 av = *reinterpret_cast<const float4*>(A + (size_t)(m0 + ar) * D_ + k0 + ac4);
        float4 wv = *reinterpret_cast<const float4*>(Wb + (size_t)(k0 + wk) * wstride + wc4);
        As[ac4 + 0][ar] = av.x;
        As[ac4 + 1][ar] = av.y;
        As[ac4 + 2][ar] = av.z;
        As[ac4 + 3][ar] = av.w;
        *reinterpret_cast<float4*>(&Ws[wk][wc4]) = wv;
        __syncthreads();

#pragma unroll
        for (int kk = 0; kk < 16; kk++) {
            float a0 = As[kk][4 * ty + 0];
            float a1 = As[kk][4 * ty + 1];
            float a2 = As[kk][4 * ty + 2];
            float a3 = As[kk][4 * ty + 3];
            float4 bv = *reinterpret_cast<const float4*>(&Ws[kk][4 * tx]);
            acc[0][0] += a0 * bv.x; acc[0][1] += a0 * bv.y; acc[0][2] += a0 * bv.z; acc[0][3] += a0 * bv.w;
            acc[1][0] += a1 * bv.x; acc[1][1] += a1 * bv.y; acc[1][2] += a1 * bv.z; acc[1][3] += a1 * bv.w;
            acc[2][0] += a2 * bv.x; acc[2][1] += a2 * bv.y; acc[2][2] += a2 * bv.z; acc[2][3] += a2 * bv.w;
            acc[3][0] += a3 * bv.x; acc[3][1] += a3 * bv.y; acc[3][2] += a3 * bv.z; acc[3][3] += a3 * bv.w;
        }
        __syncthreads();
    }

    // epilogue: + bias, write out
    float4 bb = *reinterpret_cast<const float4*>(bias + n0 + 4 * tx);
#pragma unroll
    for (int i = 0; i < 4; i++) {
        int m = m0 + 4 * ty + i;
        float4 o;
        o.x = acc[i][0] + bb.x;
        o.y = acc[i][1] + bb.y;
        o.z = acc[i][2] + bb.z;
        o.w = acc[i][3] + bb.w;
        if (PERHEAD) {
            int b = m >> 11;         // m / 2048
            int s = m & 2047;
            size_t base = ((size_t)(b * H_ + (n0 >> 6)) * S_ + s) * DK_;
            *reinterpret_cast<float4*>(C + base + 4 * tx) = o;
        } else {
            *reinterpret_cast<float4*>(C + (size_t)m * D_ + n0 + 4 * tx) = o;
        }
    }
}

// ---------------------------------------------------------------------------
// Flash-style causal attention, fp32.
// One CTA per (query-tile of 64, head, batch). Online softmax over key tiles.
// smem: Qs[64x64], KPs[64x64] (K xor-swizzled, later aliased as P), Vs[64x64]
//        = exactly 48KB.
// ---------------------------------------------------------------------------
__global__ __launch_bounds__(256) void attn_kernel(const float* __restrict__ Qg,
                                                   const float* __restrict__ Kg,
                                                   const float* __restrict__ Vg,
                                                   float* __restrict__ catg) {
    __shared__ float Qs[64 * 64];
    __shared__ float KPs[64 * 64];
    __shared__ float Vs[64 * 64];

    const int tid = threadIdx.x;
    const int tx = tid & 15;
    const int ty = tid >> 4;
    const int qt = blockIdx.x;
    const int h  = blockIdx.y;
    const int b  = blockIdx.z;
    const int q0 = qt << 6;

    const size_t headbase = (size_t)(b * H_ + h) * S_ * DK_;
    const float* Qb = Qg + headbase;
    const float* Kb = Kg + headbase;
    const float* Vb = Vg + headbase;

    // load Q tile (natural layout)
#pragma unroll
    for (int it = 0; it < 4; it++) {
        int lin = tid + (it << 8);
        int r = lin >> 4;
        int c4 = (lin & 15) << 2;
        *reinterpret_cast<float4*>(&Qs[r * 64 + c4]) =
            *reinterpret_cast<const float4*>(Qb + (size_t)(q0 + r) * DK_ + c4);
    }

    float O[4][4] = {};
    float mrow[4] = {-INFINITY, -INFINITY, -INFINITY, -INFINITY};
    float lrow[4] = {};

    for (int kt = 0; kt <= qt; kt++) {
        __syncthreads();  // prior readers of KPs/Vs done (also publishes Qs on iter 0)

        // load K tile (xor-swizzled on float4 granularity) and V tile (natural)
#pragma unroll
        for (int it = 0; it < 4; it++) {
            int lin = tid + (it << 8);
            int r = lin >> 4;       // key row 0..63
            int d4 = lin & 15;      // float4 column
            size_t goff = (size_t)((kt << 6) + r) * DK_ + (d4 << 2);
            float4 kv = *reinterpret_cast<const float4*>(Kb + goff);
            float4 vv = *reinterpret_cast<const float4*>(Vb + goff);
            int sd = (d4 ^ (r >> 2)) << 2;  // swizzle: conflict-free strided reads later
            *reinterpret_cast<float4*>(&KPs[r * 64 + sd]) = kv;
            *reinterpret_cast<float4*>(&Vs[r * 64 + (d4 << 2)]) = vv;
        }
        __syncthreads();

        // S = Q @ K^T (4x4 per thread: rows 4ty+i, keys 4tx+jj)
        float Sreg[4][4] = {};
        const float* qbase = Qs + (ty << 2) * 64;
        const int krow = (tx << 2) * 64;
#pragma unroll 8
        for (int d = 0; d < 64; d++) {
            float qa = qbase[d];
            float qb_ = qbase[64 + d];
            float qc = qbase[128 + d];
            float qd = qbase[192 + d];
            int c = ((((d >> 2) ^ tx) << 2) | (d & 3));
            float k0r = KPs[krow + c];
            float k1r = KPs[krow + 64 + c];
            float k2r = KPs[krow + 128 + c];
            float k3r = KPs[krow + 192 + c];
            Sreg[0][0] += qa * k0r; Sreg[0][1] += qa * k1r; Sreg[0][2] += qa * k2r; Sreg[0][3] += qa * k3r;
            Sreg[1][0] += qb_ * k0r; Sreg[1][1] += qb_ * k1r; Sreg[1][2] += qb_ * k2r; Sreg[1][3] += qb_ * k3r;
            Sreg[2][0] += qc * k0r; Sreg[2][1] += qc * k1r; Sreg[2][2] += qc * k2r; Sreg[2][3] += qc * k3r;
            Sreg[3][0] += qd * k0r; Sreg[3][1] += qd * k1r; Sreg[3][2] += qd * k2r; Sreg[3][3] += qd * k3r;
        }

        // scale + causal mask (only the diagonal tile needs masking)
        const bool diag = (kt == qt);
#pragma unroll
        for (int i = 0; i < 4; i++) {
#pragma unroll
            for (int j = 0; j < 4; j++) {
                float v = Sreg[i][j] * 0.125f;  // 1/sqrt(64)
                if (diag && ((kt << 6) + (tx << 2) + j) > (q0 + (ty << 2) + i)) v = -1e30f;
                Sreg[i][j] = v;
            }
        }

        // online softmax update (row groups = 16 lanes sharing ty)
        float corr[4];
#pragma unroll
        for (int i = 0; i < 4; i++) {
            float mi = fmaxf(fmaxf(Sreg[i][0], Sreg[i][1]), fmaxf(Sreg[i][2], Sreg[i][3]));
            mi = fmaxf(mi, __shfl_xor_sync(0xffffffffu, mi, 1, 16));
            mi = fmaxf(mi, __shfl_xor_sync(0xffffffffu, mi, 2, 16));
            mi = fmaxf(mi, __shfl_xor_sync(0xffffffffu, mi, 4, 16));
            mi = fmaxf(mi, __shfl_xor_sync(0xffffffffu, mi, 8, 16));
            float mnew = fmaxf(mrow[i], mi);
            float c0 = __expf(mrow[i] - mnew);
            float s = 0.f;
#pragma unroll
            for (int j = 0; j < 4; j++) {
                Sreg[i][j] = __expf(Sreg[i][j] - mnew);
                s += Sreg[i][j];
            }
            s += __shfl_xor_sync(0xffffffffu, s, 1, 16);
            s += __shfl_xor_sync(0xffffffffu, s, 2, 16);
            s += __shfl_xor_sync(0xffffffffu, s, 4, 16);
            s += __shfl_xor_sync(0xffffffffu, s, 8, 16);
            lrow[i] = lrow[i] * c0 + s;
            mrow[i] = mnew;
            corr[i] = c0;
        }
#pragma unroll
        for (int i = 0; i < 4; i++)
#pragma unroll
            for (int j = 0; j < 4; j++) O[i][j] *= corr[i];

        __syncthreads();  // all threads done reading KPs as K
        // write P into KPs (natural layout)
#pragma unroll
        for (int i = 0; i < 4; i++) {
            float4 pv = make_float4(Sreg[i][0], Sreg[i][1], Sreg[i][2], Sreg[i][3]);
            *reinterpret_cast<float4*>(&KPs[((ty << 2) + i) * 64 + (tx << 2)]) = pv;
        }
        __syncthreads();

        // O += P @ V (rows 4ty+i, dims 4tx+c)
        const float* pbase = KPs + (ty << 2) * 64;
#pragma unroll 8
        for (int j = 0; j < 64; j++) {
            float4 v = *reinterpret_cast<const float4*>(&Vs[j * 64 + (tx << 2)]);
            float p0 = pbase[j];
            float p1 = pbase[64 + j];
            float p2 = pbase[128 + j];
            float p3 = pbase[192 + j];
            O[0][0] += p0 * v.x; O[0][1] += p0 * v.y; O[0][2] += p0 * v.z; O[0][3] += p0 * v.w;
            O[1][0] += p1 * v.x; O[1][1] += p1 * v.y; O[1][2] += p1 * v.z; O[1][3] += p1 * v.w;
            O[2][0] += p2 * v.x; O[2][1] += p2 * v.y; O[2][2] += p2 * v.z; O[2][3] += p2 * v.w;
            O[3][0] += p3 * v.x; O[3][1] += p3 * v.y; O[3][2] += p3 * v.z; O[3][3] += p3 * v.w;
        }
    }

    // normalize and write in concat layout [B,S,D]: col = h*64 + d
#pragma unroll
    for (int i = 0; i < 4; i++) {
        float inv = 1.0f / lrow[i];
        float4 o = make_float4(O[i][0] * inv, O[i][1] * inv, O[i][2] * inv, O[i][3] * inv);
        int row = q0 + (ty << 2) + i;
        *reinterpret_cast<float4*>(&catg[((size_t)b * S_ + row) * D_ + (h << 6) + (tx << 2)]) = o;
    }
}

// ---------------------------------------------------------------------------
// Launch
// ---------------------------------------------------------------------------
extern "C" void kernel_launch(void* const* d_in, const int* in_sizes, int n_in,
                              void* d_out, int out_size) {
    const float* x  = (const float*)d_in[0];
    const float* Wq = (const float*)d_in[1];
    const float* bq = (const float*)d_in[2];
    const float* Wk = (const float*)d_in[3];
    const float* bk = (const float*)d_in[4];
    const float* Wv = (const float*)d_in[5];
    const float* bv = (const float*)d_in[6];
    const float* Wo = (const float*)d_in[7];
    const float* bo = (const float*)d_in[8];
    float* out = (float*)d_out;

    float *qp, *kp, *vp, *cp;
    cudaGetSymbolAddress((void**)&qp, g_Q);
    cudaGetSymbolAddress((void**)&kp, g_K);
    cudaGetSymbolAddress((void**)&vp, g_V);
    cudaGetSymbolAddress((void**)&cp, g_cat);

    dim3 gemm_grid(D_ / 64, (B_ * S_) / 64);  // (16, 128)
    proj_gemm<1><<<gemm_grid, 256>>>(x, Wq, bq, qp);
    proj_gemm<1><<<gemm_grid, 256>>>(x, Wk, bk, kp);
    proj_gemm<1><<<gemm_grid, 256>>>(x, Wv, bv, vp);

    attn_kernel<<<dim3(S_ / 64, H_, B_), 256>>>(qp, kp, vp, cp);

    proj_gemm<0><<<gemm_grid, 256>>>(cp, Wo, bo, out);
}

// round 9
// speedup vs baseline: 1.8675x; 1.8675x over previous
#include <cuda_runtime.h>
#include <math.h>
#include <cstdint>

// Problem constants
constexpr int B_  = 4;
constexpr int S_  = 2048;
constexpr int D_  = 1024;
constexpr int H_  = 16;
constexpr int DK_ = 64;
constexpr int M_  = B_ * S_;   // 8192

// ---------------------------------------------------------------------------
// Scratch (device globals: allocation-free rule)
// ---------------------------------------------------------------------------
__device__ float g_Q[(size_t)B_ * H_ * S_ * DK_];    // [B,H,S,64]
__device__ float g_K[(size_t)B_ * H_ * S_ * DK_];
__device__ float g_V[(size_t)B_ * H_ * S_ * DK_];
__device__ float g_cat[(size_t)B_ * S_ * D_];        // attention out (tf32-rounded)
__device__ float g_xr[(size_t)M_ * D_];              // tf32-rounded x
__device__ float g_WqT[(size_t)H_ * DK_ * D_];       // [h*64+n][k] K-major, tf32-rounded
__device__ float g_WkT[(size_t)H_ * DK_ * D_];
__device__ float g_WvT[(size_t)H_ * DK_ * D_];
__device__ float g_WoT[(size_t)D_ * D_];             // [n][k]

// ---------------------------------------------------------------------------
// Helpers
// ---------------------------------------------------------------------------
__device__ __forceinline__ uint32_t smem_u32(const void* p) {
    uint32_t a;
    asm("{ .reg .u64 t; cvta.to.shared.u64 t, %1; cvt.u32.u64 %0, t; }" : "=r"(a) : "l"(p));
    return a;
}
__device__ __forceinline__ float tf32r(float x) {
    uint32_t r;
    asm("cvt.rna.tf32.f32 %0, %1;" : "=r"(r) : "f"(x));
    return __uint_as_float(r);
}

#define CP16(dst, src) \
    asm volatile("cp.async.cg.shared.global [%0], [%1], 16;" :: "r"(dst), "l"(src) : "memory")
#define CP_COMMIT() asm volatile("cp.async.commit_group;" ::: "memory")
#define CP_WAIT1()  asm volatile("cp.async.wait_group 1;" ::: "memory")
#define CP_WAIT0()  asm volatile("cp.async.wait_group 0;" ::: "memory")

// tf32 warp MMA: D(16x8,f32) += A(16x8,tf32 row) * B(8x8,tf32 col)
#define MMA_TF32(c, a0, a1, a2, a3, b0, b1) \
    asm volatile( \
        "mma.sync.aligned.m16n8k8.row.col.f32.tf32.tf32.f32 " \
        "{%0,%1,%2,%3}, {%4,%5,%6,%7}, {%8,%9}, {%0,%1,%2,%3};" \
        : "+f"((c)[0]), "+f"((c)[1]), "+f"((c)[2]), "+f"((c)[3]) \
        : "r"(a0), "r"(a1), "r"(a2), "r"(a3), "r"(b0), "r"(b1))

// ---------------------------------------------------------------------------
// Prep kernels: tf32 rounding + weight transpose (to [N][K] K-major)
// ---------------------------------------------------------------------------
__global__ void round_x_kernel(const float4* __restrict__ in, float4* __restrict__ out, int n4) {
    int i = blockIdx.x * blockDim.x + threadIdx.x;
    if (i < n4) {
        float4 v = in[i];
        v.x = tf32r(v.x); v.y = tf32r(v.y); v.z = tf32r(v.z); v.w = tf32r(v.w);
        out[i] = v;
    }
}

// in: [heads][K][N] -> out: [heads][N][K], tf32-rounded. block (32,8), grid (N/32, K/32, heads)
__global__ void transpose_round_kernel(const float* __restrict__ in, float* __restrict__ out,
                                       int K, int N) {
    __shared__ float t[32][33];
    const int h = blockIdx.z;
    const float* ip = in + (size_t)h * K * N;
    float* op = out + (size_t)h * K * N;
    const int n0 = blockIdx.x * 32, k0 = blockIdx.y * 32;
#pragma unroll
    for (int i = 0; i < 4; i++)
        t[threadIdx.y + 8 * i][threadIdx.x] = ip[(size_t)(k0 + threadIdx.y + 8 * i) * N + n0 + threadIdx.x];
    __syncthreads();
#pragma unroll
    for (int i = 0; i < 4; i++)
        op[(size_t)(n0 + threadIdx.y + 8 * i) * K + k0 + threadIdx.x] = tf32r(t[threadIdx.x][threadIdx.y + 8 * i]);
}

// ---------------------------------------------------------------------------
// tf32 mma.sync GEMM:  C[M,1024] = A[M,1024] @ B^T + bias,  B stored [N][K].
// CTA tile 128x128, K-chunk 32, 256 threads (8 warps, 2x4 warp grid, 64x32/warp).
// 2-stage cp.async pipeline. smem row stride 36 floats => conflict-free frags.
// PERHEAD: scatter output to [B,H,S,64]; else dense [M,1024].
// ---------------------------------------------------------------------------
constexpr int LDS_  = 36;                 // floats per smem row
constexpr int TILEB = 128 * LDS_ * 4;     // 18432 bytes per 128x32 tile
constexpr int STAGEB = 2 * TILEB;         // A + B per stage

template <bool PERHEAD>
__global__ __launch_bounds__(256) void mm_kernel(const float* __restrict__ A,
                                                 const float* __restrict__ Bt,
                                                 const float* __restrict__ bias,
                                                 float* __restrict__ O) {
    extern __shared__ __align__(16) char smem[];
    const uint32_t sb = smem_u32(smem);
    const int tid = threadIdx.x;
    const int wid = tid >> 5, lane = tid & 31;
    const int g = lane >> 2, tg = lane & 3;       // fragment row-group / in-group id
    const int wm = wid >> 2, wn = wid & 3;        // warp grid 2 x 4
    const int m0 = blockIdx.x << 7;
    const int n0 = blockIdx.y << 7;

    float cf[4][4][4] = {};                       // [mt][nt][reg]

    // ---- async load of one 128x32 chunk pair into stage s ----
    auto load_chunk = [&](int c, int s) {
        const uint32_t stg = sb + (uint32_t)s * STAGEB;
        const int k0 = c << 5;
#pragma unroll
        for (int t = 0; t < 4; t++) {
            int idx = tid + (t << 8);             // 0..1023
            int r = idx >> 3, j = idx & 7;        // row, 16B column
            uint32_t off = (uint32_t)(r * (LDS_ * 4) + j * 16);
            CP16(stg + off, A + (size_t)(m0 + r) * D_ + k0 + j * 4);
            CP16(stg + TILEB + off, Bt + (size_t)(n0 + r) * D_ + k0 + j * 4);
        }
        CP_COMMIT();
    };

    load_chunk(0, 0);

    for (int c = 0; c < 32; c++) {
        if (c + 1 < 32) { load_chunk(c + 1, (c + 1) & 1); CP_WAIT1(); }
        else            { CP_WAIT0(); }
        __syncthreads();

        const float* As = reinterpret_cast<const float*>(smem + (size_t)(c & 1) * STAGEB);
        const float* Bs = As + TILEB / 4;

#pragma unroll
        for (int kk = 0; kk < 4; kk++) {
            const int kb = kk << 3;
            uint32_t a[4][4];
#pragma unroll
            for (int mt = 0; mt < 4; mt++) {
                const float* ap = As + (wm * 64 + mt * 16 + g) * LDS_ + kb + tg;
                a[mt][0] = __float_as_uint(ap[0]);
                a[mt][2] = __float_as_uint(ap[4]);
                a[mt][1] = __float_as_uint(ap[8 * LDS_]);
                a[mt][3] = __float_as_uint(ap[8 * LDS_ + 4]);
            }
#pragma unroll
            for (int nt = 0; nt < 4; nt++) {
                const float* bp = Bs + (wn * 32 + nt * 8 + g) * LDS_ + kb + tg;
                uint32_t b0 = __float_as_uint(bp[0]);
                uint32_t b1 = __float_as_uint(bp[4]);
#pragma unroll
                for (int mt = 0; mt < 4; mt++)
                    MMA_TF32(cf[mt][nt], a[mt][0], a[mt][1], a[mt][2], a[mt][3], b0, b1);
            }
        }
        __syncthreads();
    }

    // ---- epilogue: registers -> global (+bias), float2 stores ----
#pragma unroll
    for (int mt = 0; mt < 4; mt++) {
#pragma unroll
        for (int nt = 0; nt < 4; nt++) {
            int row0 = m0 + wm * 64 + mt * 16 + g;
            int col  = n0 + wn * 32 + nt * 8 + 2 * tg;
            float bx = bias[col], by = bias[col + 1];
            float2 lo = make_float2(cf[mt][nt][0] + bx, cf[mt][nt][1] + by);
            float2 hi = make_float2(cf[mt][nt][2] + bx, cf[mt][nt][3] + by);
            if (PERHEAD) {
                int head = col >> 6, dk = col & 63;
                int b0i = row0 >> 11, s0 = row0 & 2047;
                size_t base0 = (((size_t)(b0i * H_ + head) * S_ + s0) << 6) + dk;
                *reinterpret_cast<float2*>(O + base0) = lo;
                int row1 = row0 + 8;
                int b1i = row1 >> 11, s1 = row1 & 2047;
                size_t base1 = (((size_t)(b1i * H_ + head) * S_ + s1) << 6) + dk;
                *reinterpret_cast<float2*>(O + base1) = hi;
            } else {
                *reinterpret_cast<float2*>(O + (size_t)row0 * D_ + col) = lo;
                *reinterpret_cast<float2*>(O + (size_t)(row0 + 8) * D_ + col) = hi;
            }
        }
    }
}

// ---------------------------------------------------------------------------
// Flash-style causal attention, fp32 (tf32-rounds its output for the out-proj)
// ---------------------------------------------------------------------------
__global__ __launch_bounds__(256) void attn_kernel(const float* __restrict__ Qg,
                                                   const float* __restrict__ Kg,
                                                   const float* __restrict__ Vg,
                                                   float* __restrict__ catg) {
    __shared__ float Qs[64 * 64];
    __shared__ float KPs[64 * 64];
    __shared__ float Vs[64 * 64];

    const int tid = threadIdx.x;
    const int tx = tid & 15;
    const int ty = tid >> 4;
    const int qt = blockIdx.x;
    const int h  = blockIdx.y;
    const int b  = blockIdx.z;
    const int q0 = qt << 6;

    const size_t headbase = (size_t)(b * H_ + h) * S_ * DK_;
    const float* Qb = Qg + headbase;
    const float* Kb = Kg + headbase;
    const float* Vb = Vg + headbase;

#pragma unroll
    for (int it = 0; it < 4; it++) {
        int lin = tid + (it << 8);
        int r = lin >> 4;
        int c4 = (lin & 15) << 2;
        *reinterpret_cast<float4*>(&Qs[r * 64 + c4]) =
            *reinterpret_cast<const float4*>(Qb + (size_t)(q0 + r) * DK_ + c4);
    }

    float O[4][4] = {};
    float mrow[4] = {-INFINITY, -INFINITY, -INFINITY, -INFINITY};
    float lrow[4] = {};

    for (int kt = 0; kt <= qt; kt++) {
        __syncthreads();

#pragma unroll
        for (int it = 0; it < 4; it++) {
            int lin = tid + (it << 8);
            int r = lin >> 4;
            int d4 = lin & 15;
            size_t goff = (size_t)((kt << 6) + r) * DK_ + (d4 << 2);
            float4 kv = *reinterpret_cast<const float4*>(Kb + goff);
            float4 vv = *reinterpret_cast<const float4*>(Vb + goff);
            int sd = (d4 ^ (r >> 2)) << 2;
            *reinterpret_cast<float4*>(&KPs[r * 64 + sd]) = kv;
            *reinterpret_cast<float4*>(&Vs[r * 64 + (d4 << 2)]) = vv;
        }
        __syncthreads();

        float Sreg[4][4] = {};
        const float* qbase = Qs + (ty << 2) * 64;
        const int krow = (tx << 2) * 64;
#pragma unroll 8
        for (int d = 0; d < 64; d++) {
            float qa = qbase[d];
            float qb_ = qbase[64 + d];
            float qc = qbase[128 + d];
            float qd = qbase[192 + d];
            int c = ((((d >> 2) ^ tx) << 2) | (d & 3));
            float k0r = KPs[krow + c];
            float k1r = KPs[krow + 64 + c];
            float k2r = KPs[krow + 128 + c];
            float k3r = KPs[krow + 192 + c];
            Sreg[0][0] += qa * k0r; Sreg[0][1] += qa * k1r; Sreg[0][2] += qa * k2r; Sreg[0][3] += qa * k3r;
            Sreg[1][0] += qb_ * k0r; Sreg[1][1] += qb_ * k1r; Sreg[1][2] += qb_ * k2r; Sreg[1][3] += qb_ * k3r;
            Sreg[2][0] += qc * k0r; Sreg[2][1] += qc * k1r; Sreg[2][2] += qc * k2r; Sreg[2][3] += qc * k3r;
            Sreg[3][0] += qd * k0r; Sreg[3][1] += qd * k1r; Sreg[3][2] += qd * k2r; Sreg[3][3] += qd * k3r;
        }

        const bool diag = (kt == qt);
#pragma unroll
        for (int i = 0; i < 4; i++) {
#pragma unroll
            for (int j = 0; j < 4; j++) {
                float v = Sreg[i][j] * 0.125f;
                if (diag && ((kt << 6) + (tx << 2) + j) > (q0 + (ty << 2) + i)) v = -1e30f;
                Sreg[i][j] = v;
            }
        }

        float corr[4];
#pragma unroll
        for (int i = 0; i < 4; i++) {
            float mi = fmaxf(fmaxf(Sreg[i][0], Sreg[i][1]), fmaxf(Sreg[i][2], Sreg[i][3]));
            mi = fmaxf(mi, __shfl_xor_sync(0xffffffffu, mi, 1, 16));
            mi = fmaxf(mi, __shfl_xor_sync(0xffffffffu, mi, 2, 16));
            mi = fmaxf(mi, __shfl_xor_sync(0xffffffffu, mi, 4, 16));
            mi = fmaxf(mi, __shfl_xor_sync(0xffffffffu, mi, 8, 16));
            float mnew = fmaxf(mrow[i], mi);
            float c0 = __expf(mrow[i] - mnew);
            float s = 0.f;
#pragma unroll
            for (int j = 0; j < 4; j++) {
                Sreg[i][j] = __expf(Sreg[i][j] - mnew);
                s += Sreg[i][j];
            }
            s += __shfl_xor_sync(0xffffffffu, s, 1, 16);
            s += __shfl_xor_sync(0xffffffffu, s, 2, 16);
            s += __shfl_xor_sync(0xffffffffu, s, 4, 16);
            s += __shfl_xor_sync(0xffffffffu, s, 8, 16);
            lrow[i] = lrow[i] * c0 + s;
            mrow[i] = mnew;
            corr[i] = c0;
        }
#pragma unroll
        for (int i = 0; i < 4; i++)
#pragma unroll
            for (int j = 0; j < 4; j++) O[i][j] *= corr[i];

        __syncthreads();
#pragma unroll
        for (int i = 0; i < 4; i++) {
            float4 pv = make_float4(Sreg[i][0], Sreg[i][1], Sreg[i][2], Sreg[i][3]);
            *reinterpret_cast<float4*>(&KPs[((ty << 2) + i) * 64 + (tx << 2)]) = pv;
        }
        __syncthreads();

        const float* pbase = KPs + (ty << 2) * 64;
#pragma unroll 8
        for (int j = 0; j < 64; j++) {
            float4 v = *reinterpret_cast<const float4*>(&Vs[j * 64 + (tx << 2)]);
            float p0 = pbase[j];
            float p1 = pbase[64 + j];
            float p2 = pbase[128 + j];
            float p3 = pbase[192 + j];
            O[0][0] += p0 * v.x; O[0][1] += p0 * v.y; O[0][2] += p0 * v.z; O[0][3] += p0 * v.w;
            O[1][0] += p1 * v.x; O[1][1] += p1 * v.y; O[1][2] += p1 * v.z; O[1][3] += p1 * v.w;
            O[2][0] += p2 * v.x; O[2][1] += p2 * v.y; O[2][2] += p2 * v.z; O[2][3] += p2 * v.w;
            O[3][0] += p3 * v.x; O[3][1] += p3 * v.y; O[3][2] += p3 * v.z; O[3][3] += p3 * v.w;
        }
    }

#pragma unroll
    for (int i = 0; i < 4; i++) {
        float inv = 1.0f / lrow[i];
        float4 o = make_float4(tf32r(O[i][0] * inv), tf32r(O[i][1] * inv),
                               tf32r(O[i][2] * inv), tf32r(O[i][3] * inv));
        int row = q0 + (ty << 2) + i;
        *reinterpret_cast<float4*>(&catg[((size_t)b * S_ + row) * D_ + (h << 6) + (tx << 2)]) = o;
    }
}

// ---------------------------------------------------------------------------
// Launch
// ---------------------------------------------------------------------------
extern "C" void kernel_launch(void* const* d_in, const int* in_sizes, int n_in,
                              void* d_out, int out_size) {
    const float* x  = (const float*)d_in[0];
    const float* Wq = (const float*)d_in[1];
    const float* bq = (const float*)d_in[2];
    const float* Wk = (const float*)d_in[3];
    const float* bk = (const float*)d_in[4];
    const float* Wv = (const float*)d_in[5];
    const float* bv = (const float*)d_in[6];
    const float* Wo = (const float*)d_in[7];
    const float* bo = (const float*)d_in[8];
    float* out = (float*)d_out;

    float *qp, *kp, *vp, *cp, *xr, *wqt, *wkt, *wvt, *wot;
    cudaGetSymbolAddress((void**)&qp,  g_Q);
    cudaGetSymbolAddress((void**)&kp,  g_K);
    cudaGetSymbolAddress((void**)&vp,  g_V);
    cudaGetSymbolAddress((void**)&cp,  g_cat);
    cudaGetSymbolAddress((void**)&xr,  g_xr);
    cudaGetSymbolAddress((void**)&wqt, g_WqT);
    cudaGetSymbolAddress((void**)&wkt, g_WkT);
    cudaGetSymbolAddress((void**)&wvt, g_WvT);
    cudaGetSymbolAddress((void**)&wot, g_WoT);

    constexpr int SMEM = 2 * STAGEB;  // 73728
    cudaFuncSetAttribute(mm_kernel<true>,  cudaFuncAttributeMaxDynamicSharedMemorySize, SMEM);
    cudaFuncSetAttribute(mm_kernel<false>, cudaFuncAttributeMaxDynamicSharedMemorySize, SMEM);

    // prep: tf32 rounding + weight transposes to [N][K]
    int n4 = (M_ * D_) / 4;
    round_x_kernel<<<n4 / 256, 256>>>((const float4*)x, (float4*)xr, n4);
    dim3 tb(32, 8);
    transpose_round_kernel<<<dim3(DK_ / 32, D_ / 32, H_), tb>>>(Wq, wqt, D_, DK_);
    transpose_round_kernel<<<dim3(DK_ / 32, D_ / 32, H_), tb>>>(Wk, wkt, D_, DK_);
    transpose_round_kernel<<<dim3(DK_ / 32, D_ / 32, H_), tb>>>(Wv, wvt, D_, DK_);
    transpose_round_kernel<<<dim3(D_ / 32, D_ / 32, 1),  tb>>>(Wo, wot, D_, D_);

    dim3 grid(M_ / 128, D_ / 128);  // (64, 8)
    mm_kernel<true><<<grid, 256, SMEM>>>(xr, wqt, bq, qp);
    mm_kernel<true><<<grid, 256, SMEM>>>(xr, wkt, bk, kp);
    mm_kernel<true><<<grid, 256, SMEM>>>(xr, wvt, bv, vp);

    attn_kernel<<<dim3(S_ / 64, H_, B_), 256>>>(qp, kp, vp, cp);

    mm_kernel<false><<<grid, 256, SMEM>>>(cp, wot, bo, out);
}

// round 11
// speedup vs baseline: 3.4196x; 1.8311x over previous
#include <cuda_runtime.h>
#include <math.h>
#include <cstdint>

// Problem constants
constexpr int B_  = 4;
constexpr int S_  = 2048;
constexpr int D_  = 1024;
constexpr int H_  = 16;
constexpr int DK_ = 64;
constexpr int M_  = B_ * S_;   // 8192

// ---------------------------------------------------------------------------
// Scratch (device globals: allocation-free rule)
// ---------------------------------------------------------------------------
__device__ float g_Q[(size_t)B_ * H_ * S_ * DK_];    // [B,H,S,64] (tf32-rounded)
__device__ float g_K[(size_t)B_ * H_ * S_ * DK_];
__device__ float g_V[(size_t)B_ * H_ * S_ * DK_];
__device__ float g_cat[(size_t)B_ * S_ * D_];        // attention out (tf32-rounded)
__device__ float g_xr[(size_t)M_ * D_];              // tf32-rounded x
__device__ float g_WqT[(size_t)H_ * DK_ * D_];       // [h*64+n][k] K-major, tf32-rounded
__device__ float g_WkT[(size_t)H_ * DK_ * D_];
__device__ float g_WvT[(size_t)H_ * DK_ * D_];
__device__ float g_WoT[(size_t)D_ * D_];             // [n][k]

// ---------------------------------------------------------------------------
// Helpers
// ---------------------------------------------------------------------------
__device__ __forceinline__ uint32_t smem_u32(const void* p) {
    uint32_t a;
    asm("{ .reg .u64 t; cvta.to.shared.u64 t, %1; cvt.u32.u64 %0, t; }" : "=r"(a) : "l"(p));
    return a;
}
__device__ __forceinline__ float tf32r(float x) {
    uint32_t r;
    asm("cvt.rna.tf32.f32 %0, %1;" : "=r"(r) : "f"(x));
    return __uint_as_float(r);
}

#define CP16(dst, src) \
    asm volatile("cp.async.cg.shared.global [%0], [%1], 16;" :: "r"(dst), "l"(src) : "memory")
#define CP_COMMIT() asm volatile("cp.async.commit_group;" ::: "memory")
#define CP_WAIT1()  asm volatile("cp.async.wait_group 1;" ::: "memory")
#define CP_WAIT0()  asm volatile("cp.async.wait_group 0;" ::: "memory")

// tf32 warp MMA: D(16x8,f32) += A(16x8,tf32 row) * B(8x8,tf32 col)
#define MMA_TF32(c, a0, a1, a2, a3, b0, b1) \
    asm volatile( \
        "mma.sync.aligned.m16n8k8.row.col.f32.tf32.tf32.f32 " \
        "{%0,%1,%2,%3}, {%4,%5,%6,%7}, {%8,%9}, {%0,%1,%2,%3};" \
        : "+f"((c)[0]), "+f"((c)[1]), "+f"((c)[2]), "+f"((c)[3]) \
        : "r"(a0), "r"(a1), "r"(a2), "r"(a3), "r"(b0), "r"(b1))

// ---------------------------------------------------------------------------
// Prep kernels: tf32 rounding + weight transpose (to [N][K] K-major)
// ---------------------------------------------------------------------------
__global__ void round_x_kernel(const float4* __restrict__ in, float4* __restrict__ out, int n4) {
    int i = blockIdx.x * blockDim.x + threadIdx.x;
    if (i < n4) {
        float4 v = in[i];
        v.x = tf32r(v.x); v.y = tf32r(v.y); v.z = tf32r(v.z); v.w = tf32r(v.w);
        out[i] = v;
    }
}

// in: [heads][K][N] -> out: [heads][N][K], tf32-rounded. block (32,8), grid (N/32, K/32, heads)
__global__ void transpose_round_kernel(const float* __restrict__ in, float* __restrict__ out,
                                       int K, int N) {
    __shared__ float t[32][33];
    const int h = blockIdx.z;
    const float* ip = in + (size_t)h * K * N;
    float* op = out + (size_t)h * K * N;
    const int n0 = blockIdx.x * 32, k0 = blockIdx.y * 32;
#pragma unroll
    for (int i = 0; i < 4; i++)
        t[threadIdx.y + 8 * i][threadIdx.x] = ip[(size_t)(k0 + threadIdx.y + 8 * i) * N + n0 + threadIdx.x];
    __syncthreads();
#pragma unroll
    for (int i = 0; i < 4; i++)
        op[(size_t)(n0 + threadIdx.y + 8 * i) * K + k0 + threadIdx.x] = tf32r(t[threadIdx.x][threadIdx.y + 8 * i]);
}

// ---------------------------------------------------------------------------
// tf32 mma.sync GEMM:  C[M,1024] = A[M,1024] @ B^T + bias,  B stored [N][K].
// CTA tile 128x128, K-chunk 32, 256 threads (8 warps, 2x4 warp grid, 64x32/warp).
// 2-stage cp.async pipeline. smem row stride 36 floats => conflict-free frags.
// PERHEAD: scatter to [B,H,S,64] AND tf32-round the output (feeds tf32 attn MMA).
// ---------------------------------------------------------------------------
constexpr int LDS_  = 36;                 // floats per smem row
constexpr int TILEB = 128 * LDS_ * 4;     // 18432 bytes per 128x32 tile
constexpr int STAGEB = 2 * TILEB;         // A + B per stage

template <bool PERHEAD>
__global__ __launch_bounds__(256) void mm_kernel(const float* __restrict__ A,
                                                 const float* __restrict__ Bt,
                                                 const float* __restrict__ bias,
                                                 float* __restrict__ O) {
    extern __shared__ __align__(16) char smem[];
    const uint32_t sb = smem_u32(smem);
    const int tid = threadIdx.x;
    const int wid = tid >> 5, lane = tid & 31;
    const int g = lane >> 2, tg = lane & 3;       // fragment row-group / in-group id
    const int wm = wid >> 2, wn = wid & 3;        // warp grid 2 x 4
    const int m0 = blockIdx.x << 7;
    const int n0 = blockIdx.y << 7;

    float cf[4][4][4] = {};                       // [mt][nt][reg]

    auto load_chunk = [&](int c, int s) {
        const uint32_t stg = sb + (uint32_t)s * STAGEB;
        const int k0 = c << 5;
#pragma unroll
        for (int t = 0; t < 4; t++) {
            int idx = tid + (t << 8);             // 0..1023
            int r = idx >> 3, j = idx & 7;        // row, 16B column
            uint32_t off = (uint32_t)(r * (LDS_ * 4) + j * 16);
            CP16(stg + off, A + (size_t)(m0 + r) * D_ + k0 + j * 4);
            CP16(stg + TILEB + off, Bt + (size_t)(n0 + r) * D_ + k0 + j * 4);
        }
        CP_COMMIT();
    };

    load_chunk(0, 0);

    for (int c = 0; c < 32; c++) {
        if (c + 1 < 32) { load_chunk(c + 1, (c + 1) & 1); CP_WAIT1(); }
        else            { CP_WAIT0(); }
        __syncthreads();

        const float* As = reinterpret_cast<const float*>(smem + (size_t)(c & 1) * STAGEB);
        const float* Bs = As + TILEB / 4;

#pragma unroll
        for (int kk = 0; kk < 4; kk++) {
            const int kb = kk << 3;
            uint32_t a[4][4];
#pragma unroll
            for (int mt = 0; mt < 4; mt++) {
                const float* ap = As + (wm * 64 + mt * 16 + g) * LDS_ + kb + tg;
                a[mt][0] = __float_as_uint(ap[0]);
                a[mt][2] = __float_as_uint(ap[4]);
                a[mt][1] = __float_as_uint(ap[8 * LDS_]);
                a[mt][3] = __float_as_uint(ap[8 * LDS_ + 4]);
            }
#pragma unroll
            for (int nt = 0; nt < 4; nt++) {
                const float* bp = Bs + (wn * 32 + nt * 8 + g) * LDS_ + kb + tg;
                uint32_t b0 = __float_as_uint(bp[0]);
                uint32_t b1 = __float_as_uint(bp[4]);
#pragma unroll
                for (int mt = 0; mt < 4; mt++)
                    MMA_TF32(cf[mt][nt], a[mt][0], a[mt][1], a[mt][2], a[mt][3], b0, b1);
            }
        }
        __syncthreads();
    }

    // ---- epilogue: registers -> global (+bias), float2 stores ----
#pragma unroll
    for (int mt = 0; mt < 4; mt++) {
#pragma unroll
        for (int nt = 0; nt < 4; nt++) {
            int row0 = m0 + wm * 64 + mt * 16 + g;
            int col  = n0 + wn * 32 + nt * 8 + 2 * tg;
            float bx = bias[col], by = bias[col + 1];
            float2 lo, hi;
            if (PERHEAD) {  // rna-round: exact tf32 inputs for the attention MMA
                lo = make_float2(tf32r(cf[mt][nt][0] + bx), tf32r(cf[mt][nt][1] + by));
                hi = make_float2(tf32r(cf[mt][nt][2] + bx), tf32r(cf[mt][nt][3] + by));
            } else {
                lo = make_float2(cf[mt][nt][0] + bx, cf[mt][nt][1] + by);
                hi = make_float2(cf[mt][nt][2] + bx, cf[mt][nt][3] + by);
            }
            if (PERHEAD) {
                int head = col >> 6, dk = col & 63;
                int b0i = row0 >> 11, s0 = row0 & 2047;
                size_t base0 = (((size_t)(b0i * H_ + head) * S_ + s0) << 6) + dk;
                *reinterpret_cast<float2*>(O + base0) = lo;
                int row1 = row0 + 8;
                int b1i = row1 >> 11, s1 = row1 & 2047;
                size_t base1 = (((size_t)(b1i * H_ + head) * S_ + s1) << 6) + dk;
                *reinterpret_cast<float2*>(O + base1) = hi;
            } else {
                *reinterpret_cast<float2*>(O + (size_t)row0 * D_ + col) = lo;
                *reinterpret_cast<float2*>(O + (size_t)(row0 + 8) * D_ + col) = hi;
            }
        }
    }
}

// ---------------------------------------------------------------------------
// tf32 mma.sync flash attention, causal.
// CTA: 128 q-rows x one (b,h). 8 warps, each owns 16 q-rows (8x1 warp grid).
// Per 64-key tile: QK^T (64 MMAs/warp) -> online softmax on fragments ->
// P bounce via per-warp smem strip -> PV (64 MMAs/warp) against V^T tile.
// smem stride 68 floats (== 4 mod 32) -> conflict-free fragment loads.
// ---------------------------------------------------------------------------
constexpr int AT_ = 68;
constexpr int ATTN_SMEM = (128 * AT_ + 64 * AT_ + 64 * AT_ + 128 * AT_) * 4;  // 104448 B

__global__ __launch_bounds__(256) void attn_mma_kernel(const float* __restrict__ Qg,
                                                       const float* __restrict__ Kg,
                                                       const float* __restrict__ Vg,
                                                       float* __restrict__ catg) {
    extern __shared__ __align__(16) float sm[];
    float* Qs  = sm;                    // [128][68]  Q * 0.125
    float* Ks  = Qs + 128 * AT_;        // [64][68]   K rows t, cols d
    float* Vts = Ks + 64 * AT_;         // [64][68]   V^T: rows d, cols t
    float* Ps  = Vts + 64 * AT_;        // 8 warps x [16][68]

    const int tid = threadIdx.x, wid = tid >> 5, lane = tid & 31;
    const int g = lane >> 2, tg = lane & 3;
    const int qt = blockIdx.x, h = blockIdx.y, b = blockIdx.z;
    const int q0 = qt << 7;
    const size_t base = (size_t)(b * H_ + h) * S_ * DK_;
    const uint32_t ksb = smem_u32(Ks);

    // load Q tile, folding the 1/sqrt(64)=0.125 scale (exact power of 2)
    for (int idx = tid; idx < 128 * 16; idx += 256) {
        int r = idx >> 4, c4 = (idx & 15) << 2;
        float4 v = *reinterpret_cast<const float4*>(Qg + base + (size_t)(q0 + r) * DK_ + c4);
        float* q = Qs + r * AT_ + c4;
        q[0] = v.x * 0.125f; q[1] = v.y * 0.125f; q[2] = v.z * 0.125f; q[3] = v.w * 0.125f;
    }

    float of[8][4] = {};
    float mrow[2] = {-INFINITY, -INFINITY};
    float lrow[2] = {0.f, 0.f};
    const int row0 = q0 + (wid << 4) + g;          // rows row0 (c0/c1), row0+8 (c2/c3)
    const int ntiles = 2 * qt + 2;

    for (int kt = 0; kt < ntiles; kt++) {
        __syncthreads();  // previous tile's K/V reads done everywhere

        // K tile via cp.async, V tile transposed via regular loads (overlapped)
        for (int idx = tid; idx < 64 * 16; idx += 256) {
            int r = idx >> 4, c4 = (idx & 15) << 2;
            CP16(ksb + (uint32_t)(r * AT_ + c4) * 4,
                 Kg + base + (size_t)((kt << 6) + r) * DK_ + c4);
        }
        CP_COMMIT();
        for (int idx = tid; idx < 64 * 16; idx += 256) {
            int r = idx >> 4, c4 = (idx & 15) << 2;
            float4 v = *reinterpret_cast<const float4*>(Vg + base + (size_t)((kt << 6) + r) * DK_ + c4);
            Vts[(c4 + 0) * AT_ + r] = v.x;
            Vts[(c4 + 1) * AT_ + r] = v.y;
            Vts[(c4 + 2) * AT_ + r] = v.z;
            Vts[(c4 + 3) * AT_ + r] = v.w;
        }
        CP_WAIT0();
        __syncthreads();

        // ---- S = Q @ K^T ----
        float sf[8][4] = {};
        const float* arow = Qs + (size_t)((wid << 4) + g) * AT_;
#pragma unroll
        for (int kk = 0; kk < 8; kk++) {
            const int kb = kk << 3;
            const float* ap = arow + kb + tg;
            uint32_t a0 = __float_as_uint(ap[0]);
            uint32_t a1 = __float_as_uint(ap[8 * AT_]);
            uint32_t a2 = __float_as_uint(ap[4]);
            uint32_t a3 = __float_as_uint(ap[8 * AT_ + 4]);
#pragma unroll
            for (int nt = 0; nt < 8; nt++) {
                const float* bp = Ks + (size_t)((nt << 3) + g) * AT_ + kb + tg;
                MMA_TF32(sf[nt], a0, a1, a2, a3,
                         __float_as_uint(bp[0]), __float_as_uint(bp[4]));
            }
        }

        // ---- causal mask (only the last two key tiles can be partial) ----
        if (kt >= 2 * qt) {
            const int cbase = (kt << 6) + (tg << 1);
#pragma unroll
            for (int nt = 0; nt < 8; nt++) {
                int col = cbase + (nt << 3);
                if (col     > row0)     sf[nt][0] = -1e30f;
                if (col + 1 > row0)     sf[nt][1] = -1e30f;
                if (col     > row0 + 8) sf[nt][2] = -1e30f;
                if (col + 1 > row0 + 8) sf[nt][3] = -1e30f;
            }
        }

        // ---- online softmax on fragments (quad shuffles only) ----
        float m0 = -INFINITY, m1 = -INFINITY;
#pragma unroll
        for (int nt = 0; nt < 8; nt++) {
            m0 = fmaxf(m0, fmaxf(sf[nt][0], sf[nt][1]));
            m1 = fmaxf(m1, fmaxf(sf[nt][2], sf[nt][3]));
        }
        m0 = fmaxf(m0, __shfl_xor_sync(0xffffffffu, m0, 1, 4));
        m0 = fmaxf(m0, __shfl_xor_sync(0xffffffffu, m0, 2, 4));
        m1 = fmaxf(m1, __shfl_xor_sync(0xffffffffu, m1, 1, 4));
        m1 = fmaxf(m1, __shfl_xor_sync(0xffffffffu, m1, 2, 4));
        float mn0 = fmaxf(mrow[0], m0), mn1 = fmaxf(mrow[1], m1);
        float c0 = __expf(mrow[0] - mn0), c1 = __expf(mrow[1] - mn1);
        float s0 = 0.f, s1 = 0.f;
#pragma unroll
        for (int nt = 0; nt < 8; nt++) {
            sf[nt][0] = __expf(sf[nt][0] - mn0); s0 += sf[nt][0];
            sf[nt][1] = __expf(sf[nt][1] - mn0); s0 += sf[nt][1];
            sf[nt][2] = __expf(sf[nt][2] - mn1); s1 += sf[nt][2];
            sf[nt][3] = __expf(sf[nt][3] - mn1); s1 += sf[nt][3];
        }
        s0 += __shfl_xor_sync(0xffffffffu, s0, 1, 4);
        s0 += __shfl_xor_sync(0xffffffffu, s0, 2, 4);
        s1 += __shfl_xor_sync(0xffffffffu, s1, 1, 4);
        s1 += __shfl_xor_sync(0xffffffffu, s1, 2, 4);
        lrow[0] = lrow[0] * c0 + s0; mrow[0] = mn0;
        lrow[1] = lrow[1] * c1 + s1; mrow[1] = mn1;
#pragma unroll
        for (int nt = 0; nt < 8; nt++) {
            of[nt][0] *= c0; of[nt][1] *= c0;
            of[nt][2] *= c1; of[nt][3] *= c1;
        }

        // ---- P bounce: C-fragment layout -> A-fragment layout (per-warp strip) ----
        float* pw = Ps + (size_t)(wid << 4) * AT_;
#pragma unroll
        for (int nt = 0; nt < 8; nt++) {
            *reinterpret_cast<float2*>(pw + g * AT_ + (nt << 3) + (tg << 1)) =
                make_float2(tf32r(sf[nt][0]), tf32r(sf[nt][1]));
            *reinterpret_cast<float2*>(pw + (g + 8) * AT_ + (nt << 3) + (tg << 1)) =
                make_float2(tf32r(sf[nt][2]), tf32r(sf[nt][3]));
        }
        __syncwarp();

        // ---- O += P @ V ----
#pragma unroll
        for (int kk = 0; kk < 8; kk++) {
            const int kb = kk << 3;
            const float* ap = pw + g * AT_ + kb + tg;
            uint32_t a0 = __float_as_uint(ap[0]);
            uint32_t a1 = __float_as_uint(ap[8 * AT_]);
            uint32_t a2 = __float_as_uint(ap[4]);
            uint32_t a3 = __float_as_uint(ap[8 * AT_ + 4]);
#pragma unroll
            for (int nt = 0; nt < 8; nt++) {
                const float* bp = Vts + (size_t)((nt << 3) + g) * AT_ + kb + tg;
                MMA_TF32(of[nt], a0, a1, a2, a3,
                         __float_as_uint(bp[0]), __float_as_uint(bp[4]));
            }
        }
    }

    // ---- normalize + write concat layout [B,S,D], tf32-rounded for out-proj ----
    const float i0 = 1.0f / lrow[0], i1 = 1.0f / lrow[1];
#pragma unroll
    for (int nt = 0; nt < 8; nt++) {
        int col = (h << 6) + (nt << 3) + (tg << 1);
        *reinterpret_cast<float2*>(catg + ((size_t)b * S_ + row0) * D_ + col) =
            make_float2(tf32r(of[nt][0] * i0), tf32r(of[nt][1] * i0));
        *reinterpret_cast<float2*>(catg + ((size_t)b * S_ + row0 + 8) * D_ + col) =
            make_float2(tf32r(of[nt][2] * i1), tf32r(of[nt][3] * i1));
    }
}

// ---------------------------------------------------------------------------
// Launch
// ---------------------------------------------------------------------------
extern "C" void kernel_launch(void* const* d_in, const int* in_sizes, int n_in,
                              void* d_out, int out_size) {
    const float* x  = (const float*)d_in[0];
    const float* Wq = (const float*)d_in[1];
    const float* bq = (const float*)d_in[2];
    const float* Wk = (const float*)d_in[3];
    const float* bk = (const float*)d_in[4];
    const float* Wv = (const float*)d_in[5];
    const float* bv = (const float*)d_in[6];
    const float* Wo = (const float*)d_in[7];
    const float* bo = (const float*)d_in[8];
    float* out = (float*)d_out;

    float *qp, *kp, *vp, *cp, *xr, *wqt, *wkt, *wvt, *wot;
    cudaGetSymbolAddress((void**)&qp,  g_Q);
    cudaGetSymbolAddress((void**)&kp,  g_K);
    cudaGetSymbolAddress((void**)&vp,  g_V);
    cudaGetSymbolAddress((void**)&cp,  g_cat);
    cudaGetSymbolAddress((void**)&xr,  g_xr);
    cudaGetSymbolAddress((void**)&wqt, g_WqT);
    cudaGetSymbolAddress((void**)&wkt, g_WkT);
    cudaGetSymbolAddress((void**)&wvt, g_WvT);
    cudaGetSymbolAddress((void**)&wot, g_WoT);

    constexpr int SMEM = 2 * STAGEB;  // 73728
    cudaFuncSetAttribute(mm_kernel<true>,  cudaFuncAttributeMaxDynamicSharedMemorySize, SMEM);
    cudaFuncSetAttribute(mm_kernel<false>, cudaFuncAttributeMaxDynamicSharedMemorySize, SMEM);
    cudaFuncSetAttribute(attn_mma_kernel,  cudaFuncAttributeMaxDynamicSharedMemorySize, ATTN_SMEM);

    // prep: tf32 rounding + weight transposes to [N][K]
    int n4 = (M_ * D_) / 4;
    round_x_kernel<<<n4 / 256, 256>>>((const float4*)x, (float4*)xr, n4);
    dim3 tb(32, 8);
    transpose_round_kernel<<<dim3(DK_ / 32, D_ / 32, H_), tb>>>(Wq, wqt, D_, DK_);
    transpose_round_kernel<<<dim3(DK_ / 32, D_ / 32, H_), tb>>>(Wk, wkt, D_, DK_);
    transpose_round_kernel<<<dim3(DK_ / 32, D_ / 32, H_), tb>>>(Wv, wvt, D_, DK_);
    transpose_round_kernel<<<dim3(D_ / 32, D_ / 32, 1),  tb>>>(Wo, wot, D_, D_);

    dim3 grid(M_ / 128, D_ / 128);  // (64, 8)
    mm_kernel<true><<<grid, 256, SMEM>>>(xr, wqt, bq, qp);
    mm_kernel<true><<<grid, 256, SMEM>>>(xr, wkt, bk, kp);
    mm_kernel<true><<<grid, 256, SMEM>>>(xr, wvt, bv, vp);

    attn_mma_kernel<<<dim3(S_ / 128, H_, B_), 256, ATTN_SMEM>>>(qp, kp, vp, cp);

    mm_kernel<false><<<grid, 256, SMEM>>>(cp, wot, bo, out);
}

// round 14
// speedup vs baseline: 6.7469x; 1.9730x over previous
#include <cuda_runtime.h>
#include <cuda_fp16.h>
#include <math.h>
#include <cstdint>

// Problem constants
constexpr int B_  = 4;
constexpr int S_  = 2048;
constexpr int D_  = 1024;
constexpr int H_  = 16;
constexpr int DK_ = 64;
constexpr int M_  = B_ * S_;   // 8192

// ---------------------------------------------------------------------------
// Scratch (device globals: allocation-free rule)
// ---------------------------------------------------------------------------
__device__ __half g_Q[(size_t)B_ * H_ * S_ * DK_];   // [B,H,S,64]
__device__ __half g_K[(size_t)B_ * H_ * S_ * DK_];
__device__ __half g_V[(size_t)B_ * H_ * S_ * DK_];
__device__ __half g_cat[(size_t)B_ * S_ * D_];       // attention out, concat layout
__device__ __half g_xh[(size_t)M_ * D_];             // fp16 x
__device__ __half g_WqT[(size_t)H_ * DK_ * D_];      // [h*64+n][k] K-major fp16
__device__ __half g_WkT[(size_t)H_ * DK_ * D_];
__device__ __half g_WvT[(size_t)H_ * DK_ * D_];
__device__ __half g_WoT[(size_t)D_ * D_];            // [n][k]

// ---------------------------------------------------------------------------
// Helpers
// ---------------------------------------------------------------------------
__device__ __forceinline__ uint32_t smem_u32(const void* p) {
    uint32_t a;
    asm("{ .reg .u64 t; cvta.to.shared.u64 t, %1; cvt.u32.u64 %0, t; }" : "=r"(a) : "l"(p));
    return a;
}

#define CP16(dst, src) \
    asm volatile("cp.async.cg.shared.global [%0], [%1], 16;" :: "r"(dst), "l"(src) : "memory")
#define CP_COMMIT() asm volatile("cp.async.commit_group;" ::: "memory")
#define CP_WAIT1()  asm volatile("cp.async.wait_group 1;" ::: "memory")
#define CP_WAIT0()  asm volatile("cp.async.wait_group 0;" ::: "memory")

// fp16 warp MMA: D(16x8,f32) += A(16x16,f16 row) * B(16x8,f16 col)
#define MMA_F16(c, a0, a1, a2, a3, b0, b1) \
    asm volatile( \
        "mma.sync.aligned.m16n8k16.row.col.f32.f16.f16.f32 " \
        "{%0,%1,%2,%3}, {%4,%5,%6,%7}, {%8,%9}, {%0,%1,%2,%3};" \
        : "+f"((c)[0]), "+f"((c)[1]), "+f"((c)[2]), "+f"((c)[3]) \
        : "r"(a0), "r"(a1), "r"(a2), "r"(a3), "r"(b0), "r"(b1))

#define LDSM_X4(r0, r1, r2, r3, a) \
    asm volatile("ldmatrix.sync.aligned.m8n8.x4.shared.b16 {%0,%1,%2,%3}, [%4];" \
                 : "=r"(r0), "=r"(r1), "=r"(r2), "=r"(r3) : "r"(a))
#define LDSM_X2(r0, r1, a) \
    asm volatile("ldmatrix.sync.aligned.m8n8.x2.shared.b16 {%0,%1}, [%2];" \
                 : "=r"(r0), "=r"(r1) : "r"(a))
#define LDSM_X2T(r0, r1, a) \
    asm volatile("ldmatrix.sync.aligned.m8n8.x2.trans.shared.b16 {%0,%1}, [%2];" \
                 : "=r"(r0), "=r"(r1) : "r"(a))

// ---------------------------------------------------------------------------
// Prep kernels: fp16 (rna) conversion + weight transpose (to [N][K] K-major)
// ---------------------------------------------------------------------------
__global__ void round_x_kernel(const float4* __restrict__ in, __half2* __restrict__ out, int n4) {
    int i = blockIdx.x * blockDim.x + threadIdx.x;
    if (i < n4) {
        float4 v = in[i];
        out[2 * i]     = __floats2half2_rn(v.x, v.y);
        out[2 * i + 1] = __floats2half2_rn(v.z, v.w);
    }
}

// in: [heads][K][N] fp32 -> out: [heads][N][K] fp16. block (32,8), grid (N/32, K/32, heads)
__global__ void transpose_round_kernel(const float* __restrict__ in, __half* __restrict__ out,
                                       int K, int N) {
    __shared__ float t[32][33];
    const int h = blockIdx.z;
    const float* ip = in + (size_t)h * K * N;
    __half* op = out + (size_t)h * K * N;
    const int n0 = blockIdx.x * 32, k0 = blockIdx.y * 32;
#pragma unroll
    for (int i = 0; i < 4; i++)
        t[threadIdx.y + 8 * i][threadIdx.x] = ip[(size_t)(k0 + threadIdx.y + 8 * i) * N + n0 + threadIdx.x];
    __syncthreads();
#pragma unroll
    for (int i = 0; i < 4; i++)
        op[(size_t)(n0 + threadIdx.y + 8 * i) * K + k0 + threadIdx.x] =
            __float2half_rn(t[threadIdx.x][threadIdx.y + 8 * i]);
}

// ---------------------------------------------------------------------------
// fp16 mma.sync GEMM:  C[M,1024] = A[M,1024] @ B^T + bias,  B stored [N][K] fp16.
// CTA tile 128x128, K-chunk 64 halfs (128B rows), 256 threads (8 warps, 2x4 grid,
// 64x32/warp). 2-stage cp.async pipeline. smem stride 72 halfs (144B): ldmatrix
// row-starts hit banks 4r -> conflict-free. ldmatrix x4 (A) / x2 (B) fragments.
// PERHEAD: fp16 output scattered to [B,H,S,64]; else fp32 dense [M,1024].
// ---------------------------------------------------------------------------
constexpr int LDH   = 72;                 // halfs per smem row
constexpr int TILEB = 128 * LDH * 2;      // 18432 bytes per 128x64h tile
constexpr int STAGEB = 2 * TILEB;         // A + B per stage
constexpr int MM_SMEM = 2 * STAGEB;       // 73728

template <bool PERHEAD>
__global__ __launch_bounds__(256) void mm_kernel(const __half* __restrict__ A,
                                                 const __half* __restrict__ Bt,
                                                 const float* __restrict__ bias,
                                                 void* __restrict__ Ovoid) {
    extern __shared__ __align__(16) char smem[];
    const uint32_t sb = smem_u32(smem);
    const int tid = threadIdx.x;
    const int wid = tid >> 5, lane = tid & 31;
    const int g = lane >> 2, tg = lane & 3;
    const int wm = wid >> 2, wn = wid & 3;        // warp grid 2 x 4
    const int m0 = blockIdx.x << 7;
    const int n0 = blockIdx.y << 7;

    float cf[4][4][4] = {};                       // [mt][nt][reg]

    // per-thread ldmatrix offsets (within a stage's tile)
    const uint32_t aAo = (uint32_t)((wm * 64 + (lane & 15)) * 144 + (lane >> 4) * 16);
    const uint32_t aBo = (uint32_t)((wn * 32 + (lane & 7)) * 144 + ((lane >> 3) & 1) * 16);

    auto load_chunk = [&](int c, int s) {
        const uint32_t stg = sb + (uint32_t)s * STAGEB;
        const int k0 = c << 6;                    // 64 halfs per chunk
#pragma unroll
        for (int t = 0; t < 4; t++) {
            int idx = tid + (t << 8);             // 0..1023
            int r = idx >> 3, j = idx & 7;        // row, 16B column
            uint32_t off = (uint32_t)(r * 144 + j * 16);
            CP16(stg + off, A + (size_t)(m0 + r) * D_ + k0 + j * 8);
            CP16(stg + TILEB + off, Bt + (size_t)(n0 + r) * D_ + k0 + j * 8);
        }
        CP_COMMIT();
    };

    load_chunk(0, 0);

    for (int c = 0; c < 16; c++) {
        if (c + 1 < 16) { load_chunk(c + 1, (c + 1) & 1); CP_WAIT1(); }
        else            { CP_WAIT0(); }
        __syncthreads();

        const uint32_t As = sb + (uint32_t)(c & 1) * STAGEB;
        const uint32_t Bs = As + TILEB;

#pragma unroll
        for (int kk = 0; kk < 4; kk++) {
            uint32_t a[4][4];
#pragma unroll
            for (int mt = 0; mt < 4; mt++)
                LDSM_X4(a[mt][0], a[mt][1], a[mt][2], a[mt][3],
                        As + aAo + mt * (16 * 144) + kk * 32);
#pragma unroll
            for (int nt = 0; nt < 4; nt++) {
                uint32_t b0, b1;
                LDSM_X2(b0, b1, Bs + aBo + nt * (8 * 144) + kk * 32);
#pragma unroll
                for (int mt = 0; mt < 4; mt++)
                    MMA_F16(cf[mt][nt], a[mt][0], a[mt][1], a[mt][2], a[mt][3], b0, b1);
            }
        }
        __syncthreads();
    }

    // ---- epilogue ----
#pragma unroll
    for (int mt = 0; mt < 4; mt++) {
#pragma unroll
        for (int nt = 0; nt < 4; nt++) {
            int row0 = m0 + wm * 64 + mt * 16 + g;
            int col  = n0 + wn * 32 + nt * 8 + 2 * tg;
            float bx = bias[col], by = bias[col + 1];
            if (PERHEAD) {
                __half* O = (__half*)Ovoid;
                __half2 lo = __floats2half2_rn(cf[mt][nt][0] + bx, cf[mt][nt][1] + by);
                __half2 hi = __floats2half2_rn(cf[mt][nt][2] + bx, cf[mt][nt][3] + by);
                int head = col >> 6, dk = col & 63;
                int b0i = row0 >> 11, s0 = row0 & 2047;
                *reinterpret_cast<__half2*>(O + (((size_t)(b0i * H_ + head) * S_ + s0) << 6) + dk) = lo;
                int row1 = row0 + 8;
                int b1i = row1 >> 11, s1 = row1 & 2047;
                *reinterpret_cast<__half2*>(O + (((size_t)(b1i * H_ + head) * S_ + s1) << 6) + dk) = hi;
            } else {
                float* O = (float*)Ovoid;
                *reinterpret_cast<float2*>(O + (size_t)row0 * D_ + col) =
                    make_float2(cf[mt][nt][0] + bx, cf[mt][nt][1] + by);
                *reinterpret_cast<float2*>(O + (size_t)(row0 + 8) * D_ + col) =
                    make_float2(cf[mt][nt][2] + bx, cf[mt][nt][3] + by);
            }
        }
    }
}

// ---------------------------------------------------------------------------
// fp16 mma.sync flash attention, causal.
// CTA: 128 q-rows x one (b,h). 8 warps x 16 q-rows. Per 64-key tile:
// QK^T (ldmatrix x4/x2) -> fp32 scale+mask+online softmax on fragments ->
// P (fp16) via per-warp smem strip -> PV with ldmatrix.x2.trans on row-major V
// (no explicit transpose pass). smem stride 72 halfs -> conflict-free ldmatrix.
// ---------------------------------------------------------------------------
constexpr int ATTN_SMEM = (128 * LDH + 64 * LDH + 64 * LDH + 128 * LDH) * 2;  // 55296 B

__global__ __launch_bounds__(256) void attn_mma_kernel(const __half* __restrict__ Qg,
                                                       const __half* __restrict__ Kg,
                                                       const __half* __restrict__ Vg,
                                                       __half* __restrict__ catg) {
    extern __shared__ __align__(16) __half smh[];
    __half* Qs = smh;                   // [128][72]
    __half* Ks = Qs + 128 * LDH;        // [64][72]   rows t, cols d
    __half* Vs = Ks + 64 * LDH;         // [64][72]   rows t, cols d (row-major!)
    __half* Ps = Vs + 64 * LDH;         // 8 warps x [16][72]

    const int tid = threadIdx.x, wid = tid >> 5, lane = tid & 31;
    const int g = lane >> 2, tg = lane & 3;
    const int qt = blockIdx.x, h = blockIdx.y, b = blockIdx.z;
    const int q0 = qt << 7;
    const size_t base = (size_t)(b * H_ + h) * S_ * DK_;

    const uint32_t qsb = smem_u32(Qs), ksb = smem_u32(Ks), vsb = smem_u32(Vs), psb = smem_u32(Ps);

    // ldmatrix per-thread bases
    const int l15 = lane & 15;
    const uint32_t aQ = qsb + (uint32_t)((wid * 16 + l15) * 144 + (lane >> 4) * 16);  // +kk*32
    const uint32_t aK = ksb + (uint32_t)((lane & 7) * 144 + ((lane >> 3) & 1) * 16);  // +nt*1152+kk*32
    const uint32_t aV = vsb + (uint32_t)(l15 * 144);                                  // +kk*2304+nt*16
    const uint32_t aP = psb + (uint32_t)((wid * 16 + l15) * 144 + (lane >> 4) * 16);  // +kk*32

    // load Q tile (cp.async; waited by first tile's CP_WAIT0)
    for (int idx = tid; idx < 1024; idx += 256) {
        int r = idx >> 3, j = idx & 7;
        CP16(qsb + (uint32_t)(r * 144 + j * 16), Qg + base + (size_t)(q0 + r) * DK_ + j * 8);
    }
    CP_COMMIT();

    float of[8][4] = {};
    float mrow[2] = {-INFINITY, -INFINITY};
    float lrow[2] = {0.f, 0.f};
    const int row0 = q0 + (wid << 4) + g;
    const int ntiles = 2 * qt + 2;

    for (int kt = 0; kt < ntiles; kt++) {
        __syncthreads();  // prior tile's K/V readers done

        for (int idx = tid; idx < 512; idx += 256) {
            int r = idx >> 3, j = idx & 7;
            uint32_t off = (uint32_t)(r * 144 + j * 16);
            const __half* src = Kg + base + (size_t)((kt << 6) + r) * DK_ + j * 8;
            CP16(ksb + off, src);
            CP16(vsb + off, Vg + base + (size_t)((kt << 6) + r) * DK_ + j * 8);
        }
        CP_COMMIT();
        CP_WAIT0();
        __syncthreads();

        // ---- S = Q @ K^T ----
        float sf[8][4] = {};
#pragma unroll
        for (int kk = 0; kk < 4; kk++) {
            uint32_t a0, a1, a2, a3;
            LDSM_X4(a0, a1, a2, a3, aQ + kk * 32);
#pragma unroll
            for (int nt = 0; nt < 8; nt++) {
                uint32_t b0, b1;
                LDSM_X2(b0, b1, aK + nt * 1152 + kk * 32);
                MMA_F16(sf[nt], a0, a1, a2, a3, b0, b1);
            }
        }

        // ---- scale (1/sqrt(64)) + causal mask ----
#pragma unroll
        for (int nt = 0; nt < 8; nt++) {
            sf[nt][0] *= 0.125f; sf[nt][1] *= 0.125f;
            sf[nt][2] *= 0.125f; sf[nt][3] *= 0.125f;
        }
        if (kt >= 2 * qt) {
            const int cbase = (kt << 6) + (tg << 1);
#pragma unroll
            for (int nt = 0; nt < 8; nt++) {
                int col = cbase + (nt << 3);
                if (col     > row0)     sf[nt][0] = -1e30f;
                if (col + 1 > row0)     sf[nt][1] = -1e30f;
                if (col     > row0 + 8) sf[nt][2] = -1e30f;
                if (col + 1 > row0 + 8) sf[nt][3] = -1e30f;
            }
        }

        // ---- online softmax on fragments (quad shuffles) ----
        float m0 = -INFINITY, m1 = -INFINITY;
#pragma unroll
        for (int nt = 0; nt < 8; nt++) {
            m0 = fmaxf(m0, fmaxf(sf[nt][0], sf[nt][1]));
            m1 = fmaxf(m1, fmaxf(sf[nt][2], sf[nt][3]));
        }
        m0 = fmaxf(m0, __shfl_xor_sync(0xffffffffu, m0, 1, 4));
        m0 = fmaxf(m0, __shfl_xor_sync(0xffffffffu, m0, 2, 4));
        m1 = fmaxf(m1, __shfl_xor_sync(0xffffffffu, m1, 1, 4));
        m1 = fmaxf(m1, __shfl_xor_sync(0xffffffffu, m1, 2, 4));
        float mn0 = fmaxf(mrow[0], m0), mn1 = fmaxf(mrow[1], m1);
        float c0 = __expf(mrow[0] - mn0), c1 = __expf(mrow[1] - mn1);
        float s0 = 0.f, s1 = 0.f;
#pragma unroll
        for (int nt = 0; nt < 8; nt++) {
            sf[nt][0] = __expf(sf[nt][0] - mn0); s0 += sf[nt][0];
            sf[nt][1] = __expf(sf[nt][1] - mn0); s0 += sf[nt][1];
            sf[nt][2] = __expf(sf[nt][2] - mn1); s1 += sf[nt][2];
            sf[nt][3] = __expf(sf[nt][3] - mn1); s1 += sf[nt][3];
        }
        s0 += __shfl_xor_sync(0xffffffffu, s0, 1, 4);
        s0 += __shfl_xor_sync(0xffffffffu, s0, 2, 4);
        s1 += __shfl_xor_sync(0xffffffffu, s1, 1, 4);
        s1 += __shfl_xor_sync(0xffffffffu, s1, 2, 4);
        lrow[0] = lrow[0] * c0 + s0; mrow[0] = mn0;
        lrow[1] = lrow[1] * c1 + s1; mrow[1] = mn1;
#pragma unroll
        for (int nt = 0; nt < 8; nt++) {
            of[nt][0] *= c0; of[nt][1] *= c0;
            of[nt][2] *= c1; of[nt][3] *= c1;
        }

        // ---- P (fp16) into per-warp strip ----
        __half* pw = Ps + (size_t)(wid << 4) * LDH;
#pragma unroll
        for (int nt = 0; nt < 8; nt++) {
            *reinterpret_cast<__half2*>(pw + g * LDH + (nt << 3) + (tg << 1)) =
                __floats2half2_rn(sf[nt][0], sf[nt][1]);
            *reinterpret_cast<__half2*>(pw + (g + 8) * LDH + (nt << 3) + (tg << 1)) =
                __floats2half2_rn(sf[nt][2], sf[nt][3]);
        }
        __syncwarp();

        // ---- O += P @ V (V row-major, transposed by ldmatrix.trans) ----
#pragma unroll
        for (int kk = 0; kk < 4; kk++) {
            uint32_t a0, a1, a2, a3;
            LDSM_X4(a0, a1, a2, a3, aP + kk * 32);
#pragma unroll
            for (int nt = 0; nt < 8; nt++) {
                uint32_t b0, b1;
                LDSM_X2T(b0, b1, aV + kk * 2304 + nt * 16);
                MMA_F16(of[nt], a0, a1, a2, a3, b0, b1);
            }
        }
    }

    // ---- normalize + write concat layout [B,S,D] as fp16 ----
    const float i0 = 1.0f / lrow[0], i1 = 1.0f / lrow[1];
#pragma unroll
    for (int nt = 0; nt < 8; nt++) {
        int col = (h << 6) + (nt << 3) + (tg << 1);
        *reinterpret_cast<__half2*>(catg + ((size_t)b * S_ + row0) * D_ + col) =
            __floats2half2_rn(of[nt][0] * i0, of[nt][1] * i0);
        *reinterpret_cast<__half2*>(catg + ((size_t)b * S_ + row0 + 8) * D_ + col) =
            __floats2half2_rn(of[nt][2] * i1, of[nt][3] * i1);
    }
}

// ---------------------------------------------------------------------------
// Launch
// ---------------------------------------------------------------------------
extern "C" void kernel_launch(void* const* d_in, const int* in_sizes, int n_in,
                              void* d_out, int out_size) {
    const float* x  = (const float*)d_in[0];
    const float* Wq = (const float*)d_in[1];
    const float* bq = (const float*)d_in[2];
    const float* Wk = (const float*)d_in[3];
    const float* bk = (const float*)d_in[4];
    const float* Wv = (const float*)d_in[5];
    const float* bv = (const float*)d_in[6];
    const float* Wo = (const float*)d_in[7];
    const float* bo = (const float*)d_in[8];
    float* out = (float*)d_out;

    __half *qp, *kp, *vp, *cp, *xh, *wqt, *wkt, *wvt, *wot;
    cudaGetSymbolAddress((void**)&qp,  g_Q);
    cudaGetSymbolAddress((void**)&kp,  g_K);
    cudaGetSymbolAddress((void**)&vp,  g_V);
    cudaGetSymbolAddress((void**)&cp,  g_cat);
    cudaGetSymbolAddress((void**)&xh,  g_xh);
    cudaGetSymbolAddress((void**)&wqt, g_WqT);
    cudaGetSymbolAddress((void**)&wkt, g_WkT);
    cudaGetSymbolAddress((void**)&wvt, g_WvT);
    cudaGetSymbolAddress((void**)&wot, g_WoT);

    cudaFuncSetAttribute(mm_kernel<true>,  cudaFuncAttributeMaxDynamicSharedMemorySize, MM_SMEM);
    cudaFuncSetAttribute(mm_kernel<false>, cudaFuncAttributeMaxDynamicSharedMemorySize, MM_SMEM);
    cudaFuncSetAttribute(attn_mma_kernel,  cudaFuncAttributeMaxDynamicSharedMemorySize, ATTN_SMEM);

    // prep: fp16 conversion + weight transposes to [N][K]
    int n4 = (M_ * D_) / 4;
    round_x_kernel<<<n4 / 256, 256>>>((const float4*)x, (__half2*)xh, n4);
    dim3 tb(32, 8);
    transpose_round_kernel<<<dim3(DK_ / 32, D_ / 32, H_), tb>>>(Wq, wqt, D_, DK_);
    transpose_round_kernel<<<dim3(DK_ / 32, D_ / 32, H_), tb>>>(Wk, wkt, D_, DK_);
    transpose_round_kernel<<<dim3(DK_ / 32, D_ / 32, H_), tb>>>(Wv, wvt, D_, DK_);
    transpose_round_kernel<<<dim3(D_ / 32, D_ / 32, 1),  tb>>>(Wo, wot, D_, D_);

    dim3 grid(M_ / 128, D_ / 128);  // (64, 8)
    mm_kernel<true><<<grid, 256, MM_SMEM>>>(xh, wqt, bq, qp);
    mm_kernel<true><<<grid, 256, MM_SMEM>>>(xh, wkt, bk, kp);
    mm_kernel<true><<<grid, 256, MM_SMEM>>>(xh, wvt, bv, vp);

    attn_mma_kernel<<<dim3(S_ / 128, H_, B_), 256, ATTN_SMEM>>>(qp, kp, vp, cp);

    mm_kernel<false><<<grid, 256, MM_SMEM>>>(cp, wot, bo, out);
}